// round 14
// baseline (speedup 1.0000x reference)
#include <cuda_runtime.h>
#include <cuda_fp16.h>

#define NROWS 2048
#define DIN 256
#define H 64
#define HP 32   // h pairs

// Hidden activations in fp16, packed 8-per-entry:
// uint4 entry [ho*2048 + n], ho=0..7, holds h = 8ho..8ho+7 as 4 half2.
__device__ uint4 g_agh[8 * NROWS];
__device__ uint4 g_abh[8 * NROWS];

// ---------------------------------------------------------------------------
// Kernel 1 (fused): hidden for BOTH embeddings, 512 blocks for occupancy.
// blocks [0,256) -> ag (+b1), [256,512) -> ab. 8 rows/block.
// Thread: hp = tid&31, row r = tid>>5. Per kk: LDS.64(w) + broadcast
// LDS.32(e) + 2 FFMA. K tiled by 128. fp32 compute, half2 packed store.
// ---------------------------------------------------------------------------
__global__ void __launch_bounds__(256) hidden_kernel(
    const float* __restrict__ ag, const float* __restrict__ ab,
    const float* __restrict__ W1, const float* __restrict__ b1)
{
    __shared__ float  embs[8][128];     //  4 KB
    __shared__ float2 w1s[128][32];     // 32 KB

    const int tid = threadIdx.x;
    const int hp  = tid & 31;
    const int r   = tid >> 5;           // 0..7
    const int which = blockIdx.x >> 8;  // 0 = ag, 1 = ab
    const int n0  = (blockIdx.x & 255) * 8;
    const int koff = which ? DIN : 0;
    const float* __restrict__ emb = which ? ab : ag;

    float acc0, acc1;
    if (which == 0) {
        float2 bv = ((const float2*)b1)[hp];
        acc0 = bv.x; acc1 = bv.y;
    } else {
        acc0 = acc1 = 0.0f;
    }

    for (int kb = 0; kb < 2; kb++) {
        // emb tile: 8 x 128 = 256 float4 -> exactly 1 per thread
        {
            int er = tid >> 5, c4 = tid & 31;
            ((float4*)&embs[er][c4 * 4])[0] =
                ((const float4*)(emb + (size_t)(n0 + er) * DIN + kb * 128))[c4];
        }
        // W1 tile: 128 x 64 floats = 2048 float4 -> 8 per thread
        #pragma unroll
        for (int t = 0; t < 8; t++) {
            int idx = tid + t * 256, kk = idx >> 4, q = idx & 15;
            ((float4*)&w1s[kk][0])[q] =
                ((const float4*)(W1 + (size_t)(koff + kb * 128 + kk) * H))[q];
        }
        __syncthreads();

        #pragma unroll 16
        for (int kk = 0; kk < 128; kk++) {
            float2 w = w1s[kk][hp];
            float e = embs[r][kk];
            acc0 += e * w.x;
            acc1 += e * w.y;
        }
        __syncthreads();
    }

    // packed store: uint word (hp&3) of entry [hp>>2][n0+r]
    unsigned* outh = (unsigned*)(which ? g_abh : g_agh);
    unsigned word = (unsigned)(hp >> 2) * (NROWS * 4) + (hp & 3)
                  + (unsigned)(n0 + r) * 4;
    __half2 v = __floats2half2_rn(acc0, acc1);
    outh[word] = *(unsigned*)&v;
}

// ---------------------------------------------------------------------------
// Kernel 2 (fp16 packed): out[n,m] = sigmoid( sum_h relu(agh+abh)*W2 + b2 )
// 64x64 tile, 256 threads, 4x4 outputs/thread. Smem [ho][n] uint4 (8 h per
// entry). Two accumulator sets (ho 0-3 / 4-7) combined in fp32.
// unroll 2 on the ho loops for cross-iteration ILP (L0 overflow is cheap).
// ---------------------------------------------------------------------------
struct H2x4 { __half2 h0, h1, h2, h3; };

__device__ __forceinline__ void outer_body(
    __half2 (&acc)[4][4], int ho, int tx, int ty,
    const uint4 (*a_s)[64], const uint4 (*b_s)[64], const uint4* w2q,
    __half2 z)
{
    uint4 wv = w2q[ho];
    const H2x4 w = *(const H2x4*)&wv;
    uint4 bb[4];
    #pragma unroll
    for (int j = 0; j < 4; j++) bb[j] = b_s[ho][tx + 16 * j];
    #pragma unroll
    for (int i = 0; i < 4; i++) {
        uint4 av = a_s[ho][ty * 4 + i];
        const H2x4 a = *(const H2x4*)&av;
        #pragma unroll
        for (int j = 0; j < 4; j++) {
            const H2x4 b = *(const H2x4*)&bb[j];
            acc[i][j] = __hfma2(__hmax2(__hadd2(a.h0, b.h0), z), w.h0, acc[i][j]);
            acc[i][j] = __hfma2(__hmax2(__hadd2(a.h1, b.h1), z), w.h1, acc[i][j]);
            acc[i][j] = __hfma2(__hmax2(__hadd2(a.h2, b.h2), z), w.h2, acc[i][j]);
            acc[i][j] = __hfma2(__hmax2(__hadd2(a.h3, b.h3), z), w.h3, acc[i][j]);
        }
    }
}

__global__ void __launch_bounds__(256) outer_kernel(
    const float* __restrict__ W2, const float* __restrict__ b2,
    float* __restrict__ out)
{
    __shared__ uint4 a_s[8][64];     // 4 KB
    __shared__ uint4 b_s[8][64];     // 4 KB
    __shared__ __half2 w2s[HP];      // 128 B

    const int tid = threadIdx.x;
    const int n0 = blockIdx.y * 64;
    const int m0 = blockIdx.x * 64;

    #pragma unroll
    for (int t = 0; t < 2; t++) {
        int idx = tid + t * 256;            // 0..511
        int ho = idx >> 6, r = idx & 63;
        a_s[ho][r] = g_agh[ho * NROWS + n0 + r];
        b_s[ho][r] = g_abh[ho * NROWS + m0 + r];
    }
    if (tid < HP) w2s[tid] = __floats2half2_rn(W2[2 * tid], W2[2 * tid + 1]);
    __syncthreads();

    const int tx = tid & 15;   // m: m_local = tx + 16*j
    const int ty = tid >> 4;   // n: n_local = ty*4 + i
    const uint4* w2q = (const uint4*)w2s;
    const __half2 z = __float2half2_rn(0.0f);

    __half2 acc0[4][4], acc1[4][4];
    #pragma unroll
    for (int i = 0; i < 4; i++)
        #pragma unroll
        for (int j = 0; j < 4; j++) { acc0[i][j] = z; acc1[i][j] = z; }

    #pragma unroll 2
    for (int ho = 0; ho < 4; ho++)
        outer_body(acc0, ho, tx, ty, a_s, b_s, w2q, z);
    #pragma unroll 2
    for (int ho = 4; ho < 8; ho++)
        outer_body(acc1, ho, tx, ty, a_s, b_s, w2q, z);

    const float b2v = *b2;
    #pragma unroll
    for (int i = 0; i < 4; i++) {
        int n = n0 + ty * 4 + i;
        #pragma unroll
        for (int j = 0; j < 4; j++) {
            float2 p = __half22float2(acc0[i][j]);
            float2 q = __half22float2(acc1[i][j]);
            float logit = ((p.x + q.x) + (p.y + q.y)) + b2v;
            out[(size_t)n * 2048 + m0 + tx + 16 * j] =
                __fdividef(1.0f, 1.0f + __expf(-logit));
        }
    }
}

extern "C" void kernel_launch(void* const* d_in, const int* in_sizes, int n_in,
                              void* d_out, int out_size)
{
    const float* ag = (const float*)d_in[0];
    const float* ab = (const float*)d_in[1];
    const float* W1 = (const float*)d_in[2];
    const float* b1 = (const float*)d_in[3];
    const float* W2 = (const float*)d_in[4];
    const float* b2 = (const float*)d_in[5];
    float* out = (float*)d_out;

    hidden_kernel<<<512, 256>>>(ag, ab, W1, b1);

    dim3 grid(2048 / 64, 2048 / 64);
    outer_kernel<<<grid, 256>>>(W2, b2, out);
}